// round 4
// baseline (speedup 1.0000x reference)
#include <cuda_runtime.h>
#include <math.h>

#define BB 2
#define SS 2048
#define DD 512
#define HH 8
#define DK 64
#define M_TOTAL (BB*SS)   // 4096
#define NX (M_TOTAL*DD)   // 2097152
#define NW (DD*DD)        // 262144

// Scratch (allocation-free)
__device__ float g_Q[BB*HH*SS*DK];
__device__ float g_K[BB*HH*SS*DK];
__device__ float g_V[BB*HH*SS*DK];
__device__ float g_attn[BB*SS*DD];
// pre-split hi/lo tf32 operands
__device__ unsigned g_xh[NX],  g_xl[NX];
__device__ unsigned g_ah[NX],  g_al[NX];
__device__ unsigned g_Wqh[NW], g_Wql[NW];
__device__ unsigned g_Wkh[NW], g_Wkl[NW];
__device__ unsigned g_Wvh[NW], g_Wvl[NW];
__device__ unsigned g_Woh[NW], g_Wol[NW];

// ---------------------------------------------------------------------------
__device__ __forceinline__ unsigned f2t(float x) {
    unsigned r;
    asm("cvt.rna.tf32.f32 %0, %1;" : "=r"(r) : "f"(x));
    return r;
}

__device__ __forceinline__ void mma8(float* c,
                                     unsigned a0, unsigned a1, unsigned a2, unsigned a3,
                                     unsigned b0, unsigned b1) {
    asm volatile(
        "mma.sync.aligned.m16n8k8.row.col.f32.tf32.tf32.f32 "
        "{%0,%1,%2,%3}, {%4,%5,%6,%7}, {%8,%9}, {%0,%1,%2,%3};"
        : "+f"(c[0]), "+f"(c[1]), "+f"(c[2]), "+f"(c[3])
        : "r"(a0), "r"(a1), "r"(a2), "r"(a3), "r"(b0), "r"(b1));
}

// ---------------------------------------------------------------------------
// hi/lo tf32 split: hi = tf32(v), lo = tf32(v - hi)
// ---------------------------------------------------------------------------
__global__ __launch_bounds__(256)
void split_kernel(const float* __restrict__ in, unsigned* __restrict__ hi,
                  unsigned* __restrict__ lo, int n4) {
    const int idx = blockIdx.x * 256 + threadIdx.x;
    if (idx >= n4) return;
    float4 v = ((const float4*)in)[idx];
    float vv[4] = {v.x, v.y, v.z, v.w};
    uint4 h, l;
    unsigned* hp = &h.x; unsigned* lp = &l.x;
    #pragma unroll
    for (int j = 0; j < 4; j++) {
        unsigned hb = f2t(vv[j]);
        hp[j] = hb;
        lp[j] = f2t(vv[j] - __uint_as_float(hb));
    }
    ((uint4*)hi)[idx] = h;
    ((uint4*)lo)[idx] = l;
}

// ---------------------------------------------------------------------------
// Core 3xTF32 GEMM body on pre-split operands.
// C[M,N] = (A @ W^T + bias) * alpha.  Block 128x64, BK=32, 8 warps (4x2).
// MODE 0: row-major [M,N].  MODE 1: head-split [B,H,S,DK].
// ---------------------------------------------------------------------------
template<int MODE>
__device__ __forceinline__
void proj_body(const unsigned* __restrict__ Ah, const unsigned* __restrict__ Al_,
               const unsigned* __restrict__ Wh, const unsigned* __restrict__ Wl,
               const float* __restrict__ bias, float* __restrict__ C,
               float alpha, int m0, int n0, unsigned* sh) {
    unsigned (*Ab)[36] = (unsigned(*)[36])sh;                       // 128x36
    unsigned (*Al)[36] = (unsigned(*)[36])(sh + 128*36);            // 128x36
    unsigned (*Bb)[36] = (unsigned(*)[36])(sh + 2*128*36);          // 64x36
    unsigned (*Bl)[36] = (unsigned(*)[36])(sh + 2*128*36 + 64*36);  // 64x36

    const int tid  = threadIdx.x;
    const int lane = tid & 31;
    const int warp = tid >> 5;
    const int g = lane >> 2, c = lane & 3;
    const int wm = warp & 3, wn = warp >> 2;

    float acc[2][4][4] = {};

    for (int kt = 0; kt < 512; kt += 32) {
        __syncthreads();
        #pragma unroll
        for (int i = 0; i < 4; i++) {
            const int f = tid + i * 256;          // 0..1023
            const int r = f >> 3, col = (f & 7) * 4;
            uint4 h = *(const uint4*)(Ah + (size_t)(m0 + r) * 512 + kt + col);
            uint4 l = *(const uint4*)(Al_ + (size_t)(m0 + r) * 512 + kt + col);
            *(uint2*)&Ab[r][col]     = make_uint2(h.x, h.y);
            *(uint2*)&Ab[r][col + 2] = make_uint2(h.z, h.w);
            *(uint2*)&Al[r][col]     = make_uint2(l.x, l.y);
            *(uint2*)&Al[r][col + 2] = make_uint2(l.z, l.w);
        }
        #pragma unroll
        for (int i = 0; i < 2; i++) {
            const int f = tid + i * 256;          // 0..511
            const int r = f >> 3, col = (f & 7) * 4;
            uint4 h = *(const uint4*)(Wh + (size_t)(n0 + r) * 512 + kt + col);
            uint4 l = *(const uint4*)(Wl + (size_t)(n0 + r) * 512 + kt + col);
            *(uint2*)&Bb[r][col]     = make_uint2(h.x, h.y);
            *(uint2*)&Bb[r][col + 2] = make_uint2(h.z, h.w);
            *(uint2*)&Bl[r][col]     = make_uint2(l.x, l.y);
            *(uint2*)&Bl[r][col + 2] = make_uint2(l.z, l.w);
        }
        __syncthreads();

        #pragma unroll
        for (int d = 0; d < 4; d++) {
            const int k8 = d * 8;
            unsigned ab[2][4], al[2][4], bb[4][2], bl[4][2];
            #pragma unroll
            for (int mi = 0; mi < 2; mi++) {
                const int rb = wm * 32 + mi * 16;
                ab[mi][0] = Ab[rb + g][k8 + c];     ab[mi][1] = Ab[rb + g + 8][k8 + c];
                ab[mi][2] = Ab[rb + g][k8 + c + 4]; ab[mi][3] = Ab[rb + g + 8][k8 + c + 4];
                al[mi][0] = Al[rb + g][k8 + c];     al[mi][1] = Al[rb + g + 8][k8 + c];
                al[mi][2] = Al[rb + g][k8 + c + 4]; al[mi][3] = Al[rb + g + 8][k8 + c + 4];
            }
            #pragma unroll
            for (int ni = 0; ni < 4; ni++) {
                const int cb = wn * 32 + ni * 8;
                bb[ni][0] = Bb[cb + g][k8 + c];  bb[ni][1] = Bb[cb + g][k8 + c + 4];
                bl[ni][0] = Bl[cb + g][k8 + c];  bl[ni][1] = Bl[cb + g][k8 + c + 4];
            }
            #pragma unroll
            for (int mi = 0; mi < 2; mi++)
                #pragma unroll
                for (int ni = 0; ni < 4; ni++) {
                    mma8(acc[mi][ni], ab[mi][0], ab[mi][1], ab[mi][2], ab[mi][3], bb[ni][0], bb[ni][1]);
                    mma8(acc[mi][ni], ab[mi][0], ab[mi][1], ab[mi][2], ab[mi][3], bl[ni][0], bl[ni][1]);
                    mma8(acc[mi][ni], al[mi][0], al[mi][1], al[mi][2], al[mi][3], bb[ni][0], bb[ni][1]);
                }
        }
    }

    #pragma unroll
    for (int mi = 0; mi < 2; mi++) {
        const int r0 = m0 + wm * 32 + mi * 16 + g;
        #pragma unroll
        for (int ni = 0; ni < 4; ni++) {
            const int cc = n0 + wn * 32 + ni * 8 + c * 2;
            const float b0 = bias[cc], b1 = bias[cc + 1];
            float v[4];
            v[0] = (acc[mi][ni][0] + b0) * alpha;
            v[1] = (acc[mi][ni][1] + b1) * alpha;
            v[2] = (acc[mi][ni][2] + b0) * alpha;
            v[3] = (acc[mi][ni][3] + b1) * alpha;
            #pragma unroll
            for (int p = 0; p < 2; p++) {
                const int m = r0 + p * 8;
                #pragma unroll
                for (int q = 0; q < 2; q++) {
                    const int n = cc + q;
                    const float val = v[p * 2 + q];
                    if (MODE == 0) {
                        C[(size_t)m * 512 + n] = val;
                    } else {
                        const int b_ = m >> 11, s_ = m & 2047;
                        const int h_ = n >> 6, dk = n & 63;
                        C[(((size_t)(b_ * HH + h_)) * SS + s_) * DK + dk] = val;
                    }
                }
            }
        }
    }
}

// Fused Q/K/V projection: blockIdx.z selects the weight/bias/output triple.
__global__ __launch_bounds__(256, 2)
void qkv_kernel() {
    extern __shared__ unsigned sh[];
    const int z = blockIdx.z;
    const unsigned* Wh = (z == 0) ? g_Wqh : (z == 1) ? g_Wkh : g_Wvh;
    const unsigned* Wl = (z == 0) ? g_Wql : (z == 1) ? g_Wkl : g_Wvl;
    float* C = (z == 0) ? g_Q : (z == 1) ? g_K : g_V;
    const float alpha = (z == 0) ? 0.125f : 1.0f;
    // biases passed through globals-free path: stored at kernel launch via const args
    // (see wrapper below)
    extern __shared__ unsigned dummy[];
    (void)dummy;
    // bias pointers are supplied via parameterized variant; this symbol unused.
}

// Parameterized fused QKV (biases come from harness input pointers).
__global__ __launch_bounds__(256, 2)
void qkv_proj_kernel(const float* __restrict__ bq, const float* __restrict__ bk,
                     const float* __restrict__ bv) {
    extern __shared__ unsigned sh[];
    const int z = blockIdx.z;
    const unsigned* Wh = (z == 0) ? g_Wqh : (z == 1) ? g_Wkh : g_Wvh;
    const unsigned* Wl = (z == 0) ? g_Wql : (z == 1) ? g_Wkl : g_Wvl;
    const float* bias  = (z == 0) ? bq : (z == 1) ? bk : bv;
    float* C = (z == 0) ? g_Q : (z == 1) ? g_K : g_V;
    const float alpha = (z == 0) ? 0.125f : 1.0f;
    proj_body<1>(g_xh, g_xl, Wh, Wl, bias, C, alpha,
                 blockIdx.y * 128, blockIdx.x * 64, sh);
}

__global__ __launch_bounds__(256, 2)
void out_proj_kernel(const float* __restrict__ bo, float* __restrict__ out) {
    extern __shared__ unsigned sh[];
    proj_body<0>(g_ah, g_al, g_Woh, g_Wol, bo, out, 1.0f,
                 blockIdx.y * 128, blockIdx.x * 64, sh);
}

// ---------------------------------------------------------------------------
// Flash attention, tf32 mma. Block = 128 q-rows, 8 warps (16 rows each).
// ---------------------------------------------------------------------------
__global__ __launch_bounds__(256, 2)
void attn_kernel(const float* __restrict__ Q, const float* __restrict__ K,
                 const float* __restrict__ V, float* __restrict__ Out) {
    extern __shared__ unsigned sh[];
    unsigned (*Qs)[68] = (unsigned(*)[68])sh;                              // 128x68
    unsigned (*Ks)[68] = (unsigned(*)[68])(sh + 128*68);                   // 64x68
    unsigned (*Vs)[72] = (unsigned(*)[72])(sh + 128*68 + 64*68);           // 64x72
    unsigned (*Ps)[68] = (unsigned(*)[68])(sh + 128*68 + 64*68 + 64*72);   // 128x68

    const int tid  = threadIdx.x;
    const int lane = tid & 31;
    const int warp = tid >> 5;
    const int g = lane >> 2, c = lane & 3;
    const int wr = warp * 16;
    const int qt = blockIdx.x;    // 0..15
    const int bh = blockIdx.y;    // 0..15

    const float* Qb = Q + (size_t)bh * SS * DK + (size_t)qt * 128 * DK;
    const float* Kb = K + (size_t)bh * SS * DK;
    const float* Vb = V + (size_t)bh * SS * DK;

    #pragma unroll
    for (int i = 0; i < 8; i++) {
        const int f = tid + i * 256;
        const int r = f >> 4, col = (f & 15) * 4;
        float4 v = *(const float4*)(Qb + r * 64 + col);
        Qs[r][col]     = f2t(v.x); Qs[r][col + 1] = f2t(v.y);
        Qs[r][col + 2] = f2t(v.z); Qs[r][col + 3] = f2t(v.w);
    }

    float O[8][4] = {};
    float m0r = -1e30f, m1r = -1e30f, l0 = 0.f, l1 = 0.f;

    for (int kt = 0; kt < 32; kt++) {
        __syncthreads();
        #pragma unroll
        for (int i = 0; i < 4; i++) {
            const int f = tid + i * 256;
            const int r = f >> 4, col = (f & 15) * 4;
            float4 kv = *(const float4*)(Kb + (size_t)(kt * 64 + r) * 64 + col);
            Ks[r][col]     = f2t(kv.x); Ks[r][col + 1] = f2t(kv.y);
            Ks[r][col + 2] = f2t(kv.z); Ks[r][col + 3] = f2t(kv.w);
            float4 vv = *(const float4*)(Vb + (size_t)(kt * 64 + r) * 64 + col);
            Vs[r][col]     = f2t(vv.x); Vs[r][col + 1] = f2t(vv.y);
            Vs[r][col + 2] = f2t(vv.z); Vs[r][col + 3] = f2t(vv.w);
        }
        __syncthreads();

        float sc[8][4] = {};
        #pragma unroll
        for (int d = 0; d < 8; d++) {
            const int k8 = d * 8;
            const unsigned a0 = Qs[wr + g][k8 + c];
            const unsigned a1 = Qs[wr + g + 8][k8 + c];
            const unsigned a2 = Qs[wr + g][k8 + c + 4];
            const unsigned a3 = Qs[wr + g + 8][k8 + c + 4];
            #pragma unroll
            for (int ni = 0; ni < 8; ni++) {
                const unsigned b0 = Ks[ni * 8 + g][k8 + c];
                const unsigned b1 = Ks[ni * 8 + g][k8 + c + 4];
                mma8(sc[ni], a0, a1, a2, a3, b0, b1);
            }
        }

        {
            float mx = -1e30f;
            #pragma unroll
            for (int ni = 0; ni < 8; ni++) mx = fmaxf(mx, fmaxf(sc[ni][0], sc[ni][1]));
            mx = fmaxf(mx, __shfl_xor_sync(0xffffffffu, mx, 1));
            mx = fmaxf(mx, __shfl_xor_sync(0xffffffffu, mx, 2));
            const float mn = fmaxf(m0r, mx);
            const float corr = __expf(m0r - mn);
            m0r = mn;
            float s = 0.f;
            #pragma unroll
            for (int ni = 0; ni < 8; ni++) {
                sc[ni][0] = __expf(sc[ni][0] - mn);
                sc[ni][1] = __expf(sc[ni][1] - mn);
                s += sc[ni][0] + sc[ni][1];
            }
            s += __shfl_xor_sync(0xffffffffu, s, 1);
            s += __shfl_xor_sync(0xffffffffu, s, 2);
            l0 = l0 * corr + s;
            #pragma unroll
            for (int ni = 0; ni < 8; ni++) { O[ni][0] *= corr; O[ni][1] *= corr; }
        }
        {
            float mx = -1e30f;
            #pragma unroll
            for (int ni = 0; ni < 8; ni++) mx = fmaxf(mx, fmaxf(sc[ni][2], sc[ni][3]));
            mx = fmaxf(mx, __shfl_xor_sync(0xffffffffu, mx, 1));
            mx = fmaxf(mx, __shfl_xor_sync(0xffffffffu, mx, 2));
            const float mn = fmaxf(m1r, mx);
            const float corr = __expf(m1r - mn);
            m1r = mn;
            float s = 0.f;
            #pragma unroll
            for (int ni = 0; ni < 8; ni++) {
                sc[ni][2] = __expf(sc[ni][2] - mn);
                sc[ni][3] = __expf(sc[ni][3] - mn);
                s += sc[ni][2] + sc[ni][3];
            }
            s += __shfl_xor_sync(0xffffffffu, s, 1);
            s += __shfl_xor_sync(0xffffffffu, s, 2);
            l1 = l1 * corr + s;
            #pragma unroll
            for (int ni = 0; ni < 8; ni++) { O[ni][2] *= corr; O[ni][3] *= corr; }
        }

        #pragma unroll
        for (int ni = 0; ni < 8; ni++) {
            const int cc = ni * 8 + c * 2;
            Ps[wr + g][cc]         = f2t(sc[ni][0]);
            Ps[wr + g][cc + 1]     = f2t(sc[ni][1]);
            Ps[wr + g + 8][cc]     = f2t(sc[ni][2]);
            Ps[wr + g + 8][cc + 1] = f2t(sc[ni][3]);
        }
        __syncwarp();

        #pragma unroll
        for (int d = 0; d < 8; d++) {
            const int k8 = d * 8;
            const unsigned a0 = Ps[wr + g][k8 + c];
            const unsigned a1 = Ps[wr + g + 8][k8 + c];
            const unsigned a2 = Ps[wr + g][k8 + c + 4];
            const unsigned a3 = Ps[wr + g + 8][k8 + c + 4];
            #pragma unroll
            for (int ni = 0; ni < 8; ni++) {
                const unsigned b0 = Vs[k8 + c][ni * 8 + g];
                const unsigned b1 = Vs[k8 + c + 4][ni * 8 + g];
                mma8(O[ni], a0, a1, a2, a3, b0, b1);
            }
        }
    }

    const int b_ = bh >> 3, h_ = bh & 7;
    const float inv0 = 1.0f / l0, inv1 = 1.0f / l1;
    const int s0 = qt * 128 + wr + g;
    float* o0 = Out + ((size_t)(b_ * SS + s0)) * DD + h_ * 64;
    float* o1 = o0 + 8 * DD;
    #pragma unroll
    for (int ni = 0; ni < 8; ni++) {
        const int cc = ni * 8 + c * 2;
        o0[cc]     = O[ni][0] * inv0;
        o0[cc + 1] = O[ni][1] * inv0;
        o1[cc]     = O[ni][2] * inv1;
        o1[cc + 1] = O[ni][3] * inv1;
    }
}

// ---------------------------------------------------------------------------

extern "C" void kernel_launch(void* const* d_in, const int* in_sizes, int n_in,
                              void* d_out, int out_size) {
    const float* x  = (const float*)d_in[0];
    const float* Wq = (const float*)d_in[1];
    const float* bq = (const float*)d_in[2];
    const float* Wk = (const float*)d_in[3];
    const float* bk = (const float*)d_in[4];
    const float* Wv = (const float*)d_in[5];
    const float* bv = (const float*)d_in[6];
    const float* Wo = (const float*)d_in[7];
    const float* bo = (const float*)d_in[8];
    float* out = (float*)d_out;

    float *Q, *K, *V, *attn;
    unsigned *xh, *xl, *ah, *al;
    unsigned *Wqh, *Wql, *Wkh, *Wkl, *Wvh, *Wvl, *Woh, *Wol;
    cudaGetSymbolAddress((void**)&Q, g_Q);
    cudaGetSymbolAddress((void**)&K, g_K);
    cudaGetSymbolAddress((void**)&V, g_V);
    cudaGetSymbolAddress((void**)&attn, g_attn);
    cudaGetSymbolAddress((void**)&xh, g_xh);   cudaGetSymbolAddress((void**)&xl, g_xl);
    cudaGetSymbolAddress((void**)&ah, g_ah);   cudaGetSymbolAddress((void**)&al, g_al);
    cudaGetSymbolAddress((void**)&Wqh, g_Wqh); cudaGetSymbolAddress((void**)&Wql, g_Wql);
    cudaGetSymbolAddress((void**)&Wkh, g_Wkh); cudaGetSymbolAddress((void**)&Wkl, g_Wkl);
    cudaGetSymbolAddress((void**)&Wvh, g_Wvh); cudaGetSymbolAddress((void**)&Wvl, g_Wvl);
    cudaGetSymbolAddress((void**)&Woh, g_Woh); cudaGetSymbolAddress((void**)&Wol, g_Wol);

    const int proj_smem = (2 * 128 * 36 + 2 * 64 * 36) * 4;      // 55296 B
    const int attn_smem = (128*68 + 64*68 + 64*72 + 128*68) * 4; // 105472 B
    cudaFuncSetAttribute(qkv_proj_kernel, cudaFuncAttributeMaxDynamicSharedMemorySize, proj_smem);
    cudaFuncSetAttribute(out_proj_kernel, cudaFuncAttributeMaxDynamicSharedMemorySize, proj_smem);
    cudaFuncSetAttribute(attn_kernel,     cudaFuncAttributeMaxDynamicSharedMemorySize, attn_smem);

    // hi/lo splits (x + 4 weight matrices)
    split_kernel<<<NX/4/256, 256>>>(x,  xh,  xl,  NX/4);
    split_kernel<<<NW/4/256, 256>>>(Wq, Wqh, Wql, NW/4);
    split_kernel<<<NW/4/256, 256>>>(Wk, Wkh, Wkl, NW/4);
    split_kernel<<<NW/4/256, 256>>>(Wv, Wvh, Wvl, NW/4);
    split_kernel<<<NW/4/256, 256>>>(Wo, Woh, Wol, NW/4);

    // fused QKV projection
    qkv_proj_kernel<<<dim3(8, 32, 3), 256, proj_smem>>>(bq, bk, bv);

    // attention
    attn_kernel<<<dim3(16, 16), 256, attn_smem>>>(Q, K, V, attn);

    // split attn output, then final projection
    split_kernel<<<NX/4/256, 256>>>(attn, ah, al, NX/4);
    out_proj_kernel<<<dim3(8, 32), 256, proj_smem>>>(bo, out);
}